// round 4
// baseline (speedup 1.0000x reference)
#include <cuda_runtime.h>
#include <cuda_bf16.h>
#include <math.h>
#include <stdint.h>

#define T_TOK 8192
#define H_DIM 2048
#define HS_DIM 4096
#define P_DIM 1024
#define NE 8
#define TK (T_TOK*2)

// ======================= PTX helpers (all <= sm_80 features) =================
__device__ __forceinline__ uint32_t smem_u32(const void* p) {
    uint32_t a;
    asm("{ .reg .u64 t; cvta.to.shared.u64 t, %1; cvt.u32.u64 %0, t; }" : "=r"(a) : "l"(p));
    return a;
}
#define CP_ASYNC16(dst, src, sz) \
    asm volatile("cp.async.cg.shared.global [%0], [%1], 16, %2;" \
                 :: "r"(dst), "l"(src), "r"(sz) : "memory")
#define CP_COMMIT() asm volatile("cp.async.commit_group;" ::: "memory")
#define CP_WAIT(n)  asm volatile("cp.async.wait_group %0;" :: "n"(n) : "memory")

#define LDSM4(r0, r1, r2, r3, addr) \
    asm volatile("ldmatrix.sync.aligned.m8n8.x4.shared.b16 {%0,%1,%2,%3}, [%4];" \
                 : "=r"(r0), "=r"(r1), "=r"(r2), "=r"(r3) : "r"(addr))

#define MMA16816(d, a0, a1, a2, a3, b0, b1) \
    asm volatile("mma.sync.aligned.m16n8k16.row.col.f32.bf16.bf16.f32 " \
                 "{%0,%1,%2,%3}, {%4,%5,%6,%7}, {%8,%9}, {%0,%1,%2,%3};" \
                 : "+f"((d)[0]), "+f"((d)[1]), "+f"((d)[2]), "+f"((d)[3]) \
                 : "r"(a0), "r"(a1), "r"(a2), "r"(a3), "r"(b0), "r"(b1))

// ======================= scratch (device globals) ============================
__device__ __nv_bfloat16 g_xh[(size_t)T_TOK * H_DIM],  g_xl[(size_t)T_TOK * H_DIM];
__device__ __nv_bfloat16 g_sgh[(size_t)HS_DIM * H_DIM], g_sgl[(size_t)HS_DIM * H_DIM];
__device__ __nv_bfloat16 g_sdh[(size_t)H_DIM * HS_DIM], g_sdl[(size_t)H_DIM * HS_DIM];
__device__ __nv_bfloat16 g_uh[(size_t)T_TOK * HS_DIM],  g_ul[(size_t)T_TOK * HS_DIM];
__device__ float         g_h1[(size_t)T_TOK * H_DIM];
__device__ __nv_bfloat16 g_h1h[(size_t)T_TOK * H_DIM],  g_h1l[(size_t)T_TOK * H_DIM];
__device__ __nv_bfloat16 g_gwh[(size_t)NE * P_DIM * H_DIM], g_gwl[(size_t)NE * P_DIM * H_DIM];
__device__ __nv_bfloat16 g_dwh[(size_t)NE * H_DIM * P_DIM], g_dwl[(size_t)NE * H_DIM * P_DIM];
__device__ __nv_bfloat16 g_acth[(size_t)TK * P_DIM],    g_actl[(size_t)TK * P_DIM];
__device__ float         g_yout[(size_t)TK * H_DIM];
__device__ float g_gate[T_TOK * NE];
__device__ int   g_perm[TK];
__device__ int   g_eid[TK];
__device__ float g_cw[TK];
__device__ float g_gval[TK];
__device__ int   g_slot[TK];
__device__ int   g_sel[TK];
__device__ float g_wts[TK];
__device__ int   g_counts[NE];
__device__ int   g_offsets[NE + 1];
__device__ int   g_cursor[NE];
__device__ float g_importance[NE];

// ======================= split fp32 -> bf16 hi/lo ============================
__device__ __forceinline__ void split1(float f, unsigned short& hs, unsigned short& ls) {
    unsigned int b = __float_as_uint(f);
    hs = (unsigned short)(b >> 16);
    float lo = f - __uint_as_float(b & 0xffff0000u);
    ls = __bfloat16_as_ushort(__float2bfloat16_rn(lo));
}

__global__ void split_kernel(const float* __restrict__ s, __nv_bfloat16* __restrict__ h,
                             __nv_bfloat16* __restrict__ l, int n4) {
    int i = blockIdx.x * blockDim.x + threadIdx.x;
    if (i >= n4) return;
    float4 v = ((const float4*)s)[i];
    unsigned short h0, h1, h2, h3, l0, l1, l2, l3;
    split1(v.x, h0, l0); split1(v.y, h1, l1); split1(v.z, h2, l2); split1(v.w, h3, l3);
    ((uint2*)h)[i] = make_uint2((uint32_t)h0 | ((uint32_t)h1 << 16),
                                (uint32_t)h2 | ((uint32_t)h3 << 16));
    ((uint2*)l)[i] = make_uint2((uint32_t)l0 | ((uint32_t)l1 << 16),
                                (uint32_t)l2 | ((uint32_t)l3 << 16));
}

// ======================= small kernels =======================================
__global__ void zero_kernel() {
    int i = threadIdx.x;
    if (i < NE) { g_counts[i] = 0; g_cursor[i] = 0; g_importance[i] = 0.f; }
}

__global__ void router_kernel(const float* __restrict__ x,
                              const float* __restrict__ rw,
                              float* __restrict__ logits_out) {
    __shared__ float s_imp[NE];
    __shared__ int   s_cnt[NE];
    int tid = threadIdx.x;
    if (tid < NE) { s_imp[tid] = 0.f; s_cnt[tid] = 0; }
    __syncthreads();
    int warp = tid >> 5, lane = tid & 31;
    int t = blockIdx.x * 8 + warp;
    float acc[NE];
#pragma unroll
    for (int e = 0; e < NE; e++) acc[e] = 0.f;
    const float* xr = x + (size_t)t * H_DIM;
    for (int i = lane; i < H_DIM; i += 32) {
        float xv = xr[i];
#pragma unroll
        for (int e = 0; e < NE; e++) acc[e] += xv * rw[e * H_DIM + i];
    }
#pragma unroll
    for (int e = 0; e < NE; e++) {
#pragma unroll
        for (int o = 16; o > 0; o >>= 1) acc[e] += __shfl_xor_sync(0xffffffffu, acc[e], o);
    }
    if (lane == 0) {
        float mx = acc[0];
#pragma unroll
        for (int e = 1; e < NE; e++) mx = fmaxf(mx, acc[e]);
        float p[NE]; float s = 0.f;
#pragma unroll
        for (int e = 0; e < NE; e++) { p[e] = expf(acc[e] - mx); s += p[e]; }
        float inv = 1.f / s;
        int i0 = 0; float b0 = -1.f;
#pragma unroll
        for (int e = 0; e < NE; e++) {
            p[e] *= inv;
            logits_out[t * NE + e] = acc[e];
            if (p[e] > b0) { b0 = p[e]; i0 = e; }
        }
        int i1 = 0; float b1 = -1.f;
#pragma unroll
        for (int e = 0; e < NE; e++)
            if (e != i0 && p[e] > b1) { b1 = p[e]; i1 = e; }
        g_sel[t * 2] = i0; g_sel[t * 2 + 1] = i1;
        g_wts[t * 2] = b0; g_wts[t * 2 + 1] = b1;
#pragma unroll
        for (int e = 0; e < NE; e++) atomicAdd(&s_imp[e], p[e]);
        atomicAdd(&s_cnt[i0], 1); atomicAdd(&s_cnt[i1], 1);
    }
    __syncthreads();
    if (tid < NE) {
        atomicAdd(&g_importance[tid], s_imp[tid]);
        atomicAdd(&g_counts[tid], s_cnt[tid]);
    }
}

__global__ void offsets_kernel() {
    int off = 0;
    for (int e = 0; e < NE; e++) { g_offsets[e] = off; g_cursor[e] = off; off += g_counts[e]; }
    g_offsets[NE] = off;
}

__global__ void scatter_kernel() {
    int t = blockIdx.x * blockDim.x + threadIdx.x;
    if (t >= T_TOK) return;
#pragma unroll
    for (int k = 0; k < 2; k++) {
        int e = g_sel[t * 2 + k];
        int pos = atomicAdd(&g_cursor[e], 1);
        g_perm[pos] = t;
        g_cw[pos] = g_wts[t * 2 + k];
        g_eid[pos] = e;
        g_slot[t * 2 + k] = pos;
    }
}

__global__ void pg_kernel(const float* __restrict__ h1,
                          const float* __restrict__ pg) {
    int tid = threadIdx.x;
    int warp = tid >> 5, lane = tid & 31;
    int t = blockIdx.x * 8 + warp;
    float acc[NE];
#pragma unroll
    for (int e = 0; e < NE; e++) acc[e] = 0.f;
    const float* hr = h1 + (size_t)t * H_DIM;
    for (int i = lane; i < H_DIM; i += 32) {
        float hv = hr[i];
#pragma unroll
        for (int e = 0; e < NE; e++) acc[e] += hv * pg[e * H_DIM + i];
    }
#pragma unroll
    for (int e = 0; e < NE; e++) {
#pragma unroll
        for (int o = 16; o > 0; o >>= 1) acc[e] += __shfl_xor_sync(0xffffffffu, acc[e], o);
    }
    if (lane == 0) {
#pragma unroll
        for (int e = 0; e < NE; e++)
            g_gate[t * NE + e] = 1.f / (1.f + expf(-acc[e]));
    }
}

__global__ void gval_kernel() {
    int s = blockIdx.x * blockDim.x + threadIdx.x;
    if (s >= TK) return;
    g_gval[s] = g_gate[g_perm[s] * NE + g_eid[s]];
}

__global__ void combine_kernel(float* __restrict__ out) {
    int idx = blockIdx.x * blockDim.x + threadIdx.x;
    int t = idx / (H_DIM / 4);
    int c = (idx % (H_DIM / 4)) * 4;
    int s0 = g_slot[t * 2], s1 = g_slot[t * 2 + 1];
    float4 a = *(const float4*)&g_yout[(size_t)s0 * H_DIM + c];
    float4 b = *(const float4*)&g_yout[(size_t)s1 * H_DIM + c];
    *(float4*)&out[(size_t)t * H_DIM + c] =
        make_float4(a.x + b.x, a.y + b.y, a.z + b.z, a.w + b.w);
}

__global__ void aux_kernel(float* __restrict__ out_aux) {
    float imps = 0.f, lds = 0.f;
    float imp[NE], ld[NE];
    for (int e = 0; e < NE; e++) {
        imp[e] = g_importance[e]; ld[e] = (float)g_counts[e];
        imps += imp[e]; lds += ld[e];
    }
    float a = 0.f;
    for (int e = 0; e < NE; e++)
        a += (imp[e] / (imps + 1e-9f)) * (ld[e] / (lds + 1e-9f));
    *out_aux = (float)NE * a;
}

// ======================= bf16x3-split HMMA GEMM ==============================
// C[M,N] = A[M,K] @ B[N,K]^T  via  Ah*Bh + Ah*Bl + Al*Bh, fp32 accumulate.
// 256x128 CTA tile, BK=32, 8 warps (4x2), warp tile 64x64, m16n8k16 + ldmatrix.
// SMEM rows padded to 80B -> conflict-free ldmatrix without swizzle.
// Linear grid + supertile raster (8 m-blocks) keeps the wave's panels in L2.
// MODE 0: relu(acc)        -> Oh/Ol splits
// MODE 1: acc              -> Of fp32 + Oh/Ol splits
// MODE 2: relu(gval*acc)   -> Oh/Ol splits  (expert, A rows gathered via perm)
// MODE 3: cw*acc           -> Of fp32       (expert, A rows contiguous slots)
#define BM 256
#define BN 128
#define BK 32
#define ROWB 80
#define A_ARR (256 * ROWB)          // 20480
#define B_ARR (128 * ROWB)          // 10240
#define STAGE_B (2 * A_ARR + 2 * B_ARR)  // 61440
#define GSMEM (2 * STAGE_B)              // 122880
#define SUP 8

template<int MODE>
__global__ void __launch_bounds__(256, 1) gemm_mma(
    const __nv_bfloat16* __restrict__ Ah, const __nv_bfloat16* __restrict__ Al,
    const __nv_bfloat16* __restrict__ Bh, const __nv_bfloat16* __restrict__ Bl,
    __nv_bfloat16* __restrict__ Oh, __nv_bfloat16* __restrict__ Ol,
    float* __restrict__ Of, int N, int K, int NBn, size_t strideB) {
    extern __shared__ char smem[];
    const int tid = threadIdx.x;
    const int wid = tid >> 5, lane = tid & 31;
    const int warp_m = wid & 3;          // 4 warps over M (64 rows each)
    const int warp_n = wid >> 2;         // 2 warps over N (64 cols each)

    int mb, nb;
    if (MODE >= 2) { mb = blockIdx.x; nb = blockIdx.y; }
    else {
        const int bx = blockIdx.x;
        const int per = SUP * NBn;
        const int grp = bx / per, rem = bx % per;
        mb = grp * SUP + (rem % SUP);
        nb = rem / SUP;
    }

    int cnt = BM, base = 0;
    const int m0i = mb * BM;
    const int n0i = nb * BN;
    if (MODE >= 2) {
        int e = blockIdx.z;
        cnt = g_counts[e]; base = g_offsets[e];
        if (m0i >= cnt) return;
        Bh += (size_t)e * strideB;
        Bl += (size_t)e * strideB;
    }

    // ---- gmem->smem mapping: A row = tid (4x16B), B row = tid>>1 (2x16B) ----
    long aRow;
    if (MODE == 2) { int r = m0i + tid; aRow = (r < cnt) ? (long)g_perm[base + r] : -1; }
    else if (MODE == 3) { int r = m0i + tid; aRow = (r < cnt) ? (long)(base + r) : -1; }
    else aRow = (long)(m0i + tid);
    const uint32_t aSz = (aRow >= 0) ? 16u : 0u;
    const size_t aRowC = (size_t)(aRow >= 0 ? aRow : 0);
    const size_t bRow = (size_t)(n0i + (tid >> 1));
    const uint32_t bCh = (uint32_t)(tid & 1) * 2;   // 16B-chunk pair base (0 or 2)

    const uint32_t sb = smem_u32(smem);
    const uint32_t daOff = (uint32_t)tid * ROWB;
    const uint32_t dbOff = (uint32_t)(tid >> 1) * ROWB + bCh * 16;

    // ---- ldmatrix lane addresses --------------------------------------------
    const int rA = (lane & 7) + ((lane >> 3) & 1) * 8;
    const uint32_t kcA = (uint32_t)(lane >> 4) * 16;
    uint32_t aoff[4];
#pragma unroll
    for (int mt = 0; mt < 4; mt++)
        aoff[mt] = (uint32_t)(warp_m * 64 + mt * 16 + rA) * ROWB + kcA;
    // B x4 covers two adjacent n-tiles (16 rows)
    uint32_t boff[4];
#pragma unroll
    for (int ntp = 0; ntp < 4; ntp++)
        boff[ntp] = (uint32_t)(warp_n * 64 + ntp * 16 + ((lane >> 4) & 1) * 8 + (lane & 7)) * ROWB
                  + (uint32_t)((lane >> 3) & 1) * 16;

    float acc[4][8][4];
#pragma unroll
    for (int mt = 0; mt < 4; mt++)
#pragma unroll
        for (int nt = 0; nt < 8; nt++)
#pragma unroll
            for (int q = 0; q < 4; q++) acc[mt][nt][q] = 0.f;

    const int nk = K / BK;

#define PREFETCH(stage, cIdx) do {                                              \
        const size_t ko = (size_t)(cIdx) * BK;                                  \
        const uint32_t st0 = sb + (stage) * STAGE_B;                            \
        const __nv_bfloat16* pah = Ah + aRowC * K + ko;                         \
        const __nv_bfloat16* pal = Al + aRowC * K + ko;                         \
        const uint32_t da = st0 + daOff;                                        \
        CP_ASYNC16(da,      pah,      aSz);  CP_ASYNC16(da + 16, pah + 8,  aSz);\
        CP_ASYNC16(da + 32, pah + 16, aSz);  CP_ASYNC16(da + 48, pah + 24, aSz);\
        CP_ASYNC16(da + A_ARR,      pal,      aSz);                             \
        CP_ASYNC16(da + A_ARR + 16, pal + 8,  aSz);                             \
        CP_ASYNC16(da + A_ARR + 32, pal + 16, aSz);                             \
        CP_ASYNC16(da + A_ARR + 48, pal + 24, aSz);                             \
        const __nv_bfloat16* pbh = Bh + bRow * K + ko + bCh * 8;                \
        const __nv_bfloat16* pbl = Bl + bRow * K + ko + bCh * 8;                \
        const uint32_t db = st0 + 2 * A_ARR + dbOff;                            \
        CP_ASYNC16(db,      pbh,     16u);  CP_ASYNC16(db + 16, pbh + 8, 16u);  \
        CP_ASYNC16(db + B_ARR,      pbl,     16u);                              \
        CP_ASYNC16(db + B_ARR + 16, pbl + 8, 16u);                              \
    } while (0)

    PREFETCH(0, 0);
    CP_COMMIT();

    for (int c = 0; c < nk; ++c) {
        if (c + 1 < nk) {
            PREFETCH((c + 1) & 1, c + 1);
            CP_COMMIT();
            CP_WAIT(1);
        } else {
            CP_WAIT(0);
        }
        __syncthreads();
        const uint32_t st = sb + (uint32_t)(c & 1) * STAGE_B;
#pragma unroll
        for (int ks = 0; ks < 2; ++ks) {
            const uint32_t kb = (uint32_t)ks * 32;
            uint32_t ah[4][4], bh[4][4], bl[4][4];
#pragma unroll
            for (int mt = 0; mt < 4; mt++)
                LDSM4(ah[mt][0], ah[mt][1], ah[mt][2], ah[mt][3], st + aoff[mt] + kb);
#pragma unroll
            for (int ntp = 0; ntp < 4; ntp++)
                LDSM4(bh[ntp][0], bh[ntp][1], bh[ntp][2], bh[ntp][3],
                      st + 2 * A_ARR + boff[ntp] + kb);
#pragma unroll
            for (int ntp = 0; ntp < 4; ntp++)
                LDSM4(bl[ntp][0], bl[ntp][1], bl[ntp][2], bl[ntp][3],
                      st + 2 * A_ARR + B_ARR + boff[ntp] + kb);
            // hi*hi and hi*lo
#pragma unroll
            for (int mt = 0; mt < 4; mt++)
#pragma unroll
                for (int nt = 0; nt < 8; nt++) {
                    const int p = nt >> 1, w = (nt & 1) * 2;
                    MMA16816(acc[mt][nt], ah[mt][0], ah[mt][1], ah[mt][2], ah[mt][3],
                             bh[p][w], bh[p][w + 1]);
                    MMA16816(acc[mt][nt], ah[mt][0], ah[mt][1], ah[mt][2], ah[mt][3],
                             bl[p][w], bl[p][w + 1]);
                }
            // lo*hi (load al after bl is dead)
            uint32_t al[4][4];
#pragma unroll
            for (int mt = 0; mt < 4; mt++)
                LDSM4(al[mt][0], al[mt][1], al[mt][2], al[mt][3],
                      st + A_ARR + aoff[mt] + kb);
#pragma unroll
            for (int mt = 0; mt < 4; mt++)
#pragma unroll
                for (int nt = 0; nt < 8; nt++) {
                    const int p = nt >> 1, w = (nt & 1) * 2;
                    MMA16816(acc[mt][nt], al[mt][0], al[mt][1], al[mt][2], al[mt][3],
                             bh[p][w], bh[p][w + 1]);
                }
        }
        __syncthreads();
    }
#undef PREFETCH

    // ---- epilogue ------------------------------------------------------------
    const int colBase = n0i + warp_n * 64 + (lane & 3) * 2;
#pragma unroll
    for (int mt = 0; mt < 4; mt++) {
#pragma unroll
        for (int h = 0; h < 2; h++) {
            const int rloc = warp_m * 64 + mt * 16 + (lane >> 2) + h * 8;
            const int r = m0i + rloc;
            size_t orow = (size_t)r;
            float scale = 1.f;
            if (MODE >= 2) {
                if (r >= cnt) continue;
                orow = (size_t)base + r;
                scale = (MODE == 2) ? g_gval[orow] : g_cw[orow];
            }
#pragma unroll
            for (int nt = 0; nt < 8; nt++) {
                float v0 = acc[mt][nt][h * 2];
                float v1 = acc[mt][nt][h * 2 + 1];
                if (MODE == 0) { v0 = fmaxf(v0, 0.f); v1 = fmaxf(v1, 0.f); }
                else if (MODE == 2) { v0 = fmaxf(scale * v0, 0.f); v1 = fmaxf(scale * v1, 0.f); }
                else if (MODE == 3) { v0 *= scale; v1 *= scale; }
                const size_t o = orow * N + colBase + nt * 8;
                if (MODE == 1 || MODE == 3)
                    *(float2*)(Of + o) = make_float2(v0, v1);
                if (MODE != 3) {
                    unsigned short h0, l0, h1_, l1_;
                    split1(v0, h0, l0); split1(v1, h1_, l1_);
                    *(uint32_t*)(Oh + o) = (uint32_t)h0 | ((uint32_t)h1_ << 16);
                    *(uint32_t*)(Ol + o) = (uint32_t)l0 | ((uint32_t)l1_ << 16);
                }
            }
        }
    }
}

// ======================= launch ==============================================
extern "C" void kernel_launch(void* const* d_in, const int* in_sizes, int n_in,
                              void* d_out, int out_size) {
    const float* x  = (const float*)d_in[0];  // [T, H]
    const float* rw = (const float*)d_in[1];  // [E, H]
    const float* sg = (const float*)d_in[2];  // [HS, H]
    const float* sd = (const float*)d_in[3];  // [H, HS]
    const float* pg = (const float*)d_in[4];  // [E, H]
    const float* gw = (const float*)d_in[5];  // [E, P, H]
    const float* dw = (const float*)d_in[6];  // [E, H, P]

    float* out        = (float*)d_out;
    float* out_logits = out + (size_t)T_TOK * H_DIM;
    float* out_aux    = out_logits + (size_t)T_TOK * NE;

    __nv_bfloat16 *xh, *xl, *sgh, *sgl, *sdh, *sdl, *uh, *ul, *h1h, *h1l,
                  *gwh, *gwl, *dwh, *dwl, *acth, *actl;
    float *h1, *yout;
    cudaGetSymbolAddress((void**)&xh, g_xh);   cudaGetSymbolAddress((void**)&xl, g_xl);
    cudaGetSymbolAddress((void**)&sgh, g_sgh); cudaGetSymbolAddress((void**)&sgl, g_sgl);
    cudaGetSymbolAddress((void**)&sdh, g_sdh); cudaGetSymbolAddress((void**)&sdl, g_sdl);
    cudaGetSymbolAddress((void**)&uh, g_uh);   cudaGetSymbolAddress((void**)&ul, g_ul);
    cudaGetSymbolAddress((void**)&h1h, g_h1h); cudaGetSymbolAddress((void**)&h1l, g_h1l);
    cudaGetSymbolAddress((void**)&gwh, g_gwh); cudaGetSymbolAddress((void**)&gwl, g_gwl);
    cudaGetSymbolAddress((void**)&dwh, g_dwh); cudaGetSymbolAddress((void**)&dwl, g_dwl);
    cudaGetSymbolAddress((void**)&acth, g_acth); cudaGetSymbolAddress((void**)&actl, g_actl);
    cudaGetSymbolAddress((void**)&h1, g_h1);   cudaGetSymbolAddress((void**)&yout, g_yout);

    cudaFuncSetAttribute(gemm_mma<0>, cudaFuncAttributeMaxDynamicSharedMemorySize, GSMEM);
    cudaFuncSetAttribute(gemm_mma<1>, cudaFuncAttributeMaxDynamicSharedMemorySize, GSMEM);
    cudaFuncSetAttribute(gemm_mma<2>, cudaFuncAttributeMaxDynamicSharedMemorySize, GSMEM);
    cudaFuncSetAttribute(gemm_mma<3>, cudaFuncAttributeMaxDynamicSharedMemorySize, GSMEM);

    // split inputs to bf16 hi/lo
    {
        int n4;
        n4 = T_TOK * H_DIM / 4;      split_kernel<<<(n4 + 255) / 256, 256>>>(x,  xh,  xl,  n4);
        n4 = HS_DIM * H_DIM / 4;     split_kernel<<<(n4 + 255) / 256, 256>>>(sg, sgh, sgl, n4);
        n4 = H_DIM * HS_DIM / 4;     split_kernel<<<(n4 + 255) / 256, 256>>>(sd, sdh, sdl, n4);
        n4 = NE * P_DIM * H_DIM / 4; split_kernel<<<(n4 + 255) / 256, 256>>>(gw, gwh, gwl, n4);
        n4 = NE * H_DIM * P_DIM / 4; split_kernel<<<(n4 + 255) / 256, 256>>>(dw, dwh, dwl, n4);
    }

    zero_kernel<<<1, 32>>>();
    router_kernel<<<T_TOK / 8, 256>>>(x, rw, out_logits);
    offsets_kernel<<<1, 1>>>();
    scatter_kernel<<<T_TOK / 256, 256>>>();

    // u = relu(x @ sg^T)   [T, HS] -> splits
    {
        int MB = T_TOK / BM, NB = HS_DIM / BN;
        gemm_mma<0><<<MB * NB, 256, GSMEM>>>(xh, xl, sgh, sgl, uh, ul, nullptr,
                                             HS_DIM, H_DIM, NB, 0);
    }
    // h1 = u @ sd^T        [T, H]  -> fp32 + splits
    {
        int MB = T_TOK / BM, NB = H_DIM / BN;
        gemm_mma<1><<<MB * NB, 256, GSMEM>>>(uh, ul, sdh, sdl, h1h, h1l, h1,
                                             H_DIM, HS_DIM, NB, 0);
    }
    pg_kernel<<<T_TOK / 8, 256>>>(h1, pg);
    gval_kernel<<<TK / 256, 256>>>();

    // act = relu(g * (h1[perm] @ g_w[e]^T))   [TK, P] -> splits
    {
        dim3 g(T_TOK / BM, P_DIM / BN, NE);
        gemm_mma<2><<<g, 256, GSMEM>>>(h1h, h1l, gwh, gwl, acth, actl, nullptr,
                                       P_DIM, H_DIM, P_DIM / BN, (size_t)P_DIM * H_DIM);
    }
    // yout = cw * (act @ d_w[e]^T)            [TK, H] -> fp32
    {
        dim3 g(T_TOK / BM, H_DIM / BN, NE);
        gemm_mma<3><<<g, 256, GSMEM>>>(acth, actl, dwh, dwl, nullptr, nullptr, yout,
                                       H_DIM, P_DIM, H_DIM / BN, (size_t)H_DIM * P_DIM);
    }
    combine_kernel<<<(T_TOK * H_DIM / 4) / 256, 256>>>(out);
    aux_kernel<<<1, 1>>>(out_aux);
}

// round 5
// speedup vs baseline: 1.9417x; 1.9417x over previous
#include <cuda_runtime.h>
#include <math.h>
#include <stdint.h>

#define T_TOK 8192
#define H_DIM 2048
#define HS_DIM 4096
#define P_DIM 1024
#define NE 8
#define TK (T_TOK*2)

// ======================= PTX helpers (all <= sm_80 features) =================
__device__ __forceinline__ uint32_t smem_u32(const void* p) {
    uint32_t a;
    asm("{ .reg .u64 t; cvta.to.shared.u64 t, %1; cvt.u32.u64 %0, t; }" : "=r"(a) : "l"(p));
    return a;
}
#define CP_ASYNC16(dst, src, sz) \
    asm volatile("cp.async.cg.shared.global [%0], [%1], 16, %2;" \
                 :: "r"(dst), "l"(src), "r"(sz) : "memory")
#define CP_COMMIT() asm volatile("cp.async.commit_group;" ::: "memory")
#define CP_WAIT(n)  asm volatile("cp.async.wait_group %0;" :: "n"(n) : "memory")

#define LDSM4(r0, r1, r2, r3, addr) \
    asm volatile("ldmatrix.sync.aligned.m8n8.x4.shared.b16 {%0,%1,%2,%3}, [%4];" \
                 : "=r"(r0), "=r"(r1), "=r"(r2), "=r"(r3) : "r"(addr))

#define MMAS8(d, a0_, a1_, a2_, a3_, b0_, b1_) \
    asm volatile("mma.sync.aligned.m16n8k32.row.col.s32.s8.s8.s32 " \
                 "{%0,%1,%2,%3}, {%4,%5,%6,%7}, {%8,%9}, {%0,%1,%2,%3};" \
                 : "+r"((d)[0]), "+r"((d)[1]), "+r"((d)[2]), "+r"((d)[3]) \
                 : "r"(a0_), "r"(a1_), "r"(a2_), "r"(a3_), "r"(b0_), "r"(b1_))

// ======================= scratch (device globals) ============================
// int8 limb pairs + per-row scales for every GEMM operand
__device__ int8_t g_x1[(size_t)T_TOK * H_DIM],   g_x0[(size_t)T_TOK * H_DIM];
__device__ float  g_sx[T_TOK];
__device__ int8_t g_sg1[(size_t)HS_DIM * H_DIM], g_sg0[(size_t)HS_DIM * H_DIM];
__device__ float  g_ssg[HS_DIM];
__device__ int8_t g_sd1[(size_t)H_DIM * HS_DIM], g_sd0[(size_t)H_DIM * HS_DIM];
__device__ float  g_ssd[H_DIM];
__device__ int8_t g_gw1[(size_t)NE * P_DIM * H_DIM], g_gw0[(size_t)NE * P_DIM * H_DIM];
__device__ float  g_sgw[NE * P_DIM];
__device__ int8_t g_dw1[(size_t)NE * H_DIM * P_DIM], g_dw0[(size_t)NE * H_DIM * P_DIM];
__device__ float  g_sdw[NE * H_DIM];
__device__ float  g_u[(size_t)T_TOK * HS_DIM];
__device__ int8_t g_u1[(size_t)T_TOK * HS_DIM],  g_u0[(size_t)T_TOK * HS_DIM];
__device__ float  g_su[T_TOK];
__device__ float  g_h1[(size_t)T_TOK * H_DIM];
__device__ int8_t g_h11[(size_t)T_TOK * H_DIM],  g_h10[(size_t)T_TOK * H_DIM];
__device__ float  g_sh1[T_TOK];
__device__ float  g_act[(size_t)TK * P_DIM];
__device__ int8_t g_a1[(size_t)TK * P_DIM],      g_a0[(size_t)TK * P_DIM];
__device__ float  g_sact[TK];
__device__ float  g_yout[(size_t)TK * H_DIM];
__device__ float g_gate[T_TOK * NE];
__device__ int   g_perm[TK];
__device__ int   g_eid[TK];
__device__ float g_cw[TK];
__device__ float g_gval[TK];
__device__ int   g_slot[TK];
__device__ int   g_sel[TK];
__device__ float g_wts[TK];
__device__ int   g_counts[NE];
__device__ int   g_offsets[NE + 1];
__device__ int   g_cursor[NE];
__device__ float g_importance[NE];

// ======================= per-row two-limb int8 quantization ==================
// q = round(v * 32512 / rowmax), limbs: q = a1*256 + a0  (both s8)
__global__ void quant_rows(const float* __restrict__ src, int K4,
                           int8_t* __restrict__ q1, int8_t* __restrict__ q0,
                           float* __restrict__ scale) {
    const int row = blockIdx.x;
    const float4* r = (const float4*)src + (size_t)row * K4;
    float mx = 0.f;
    for (int i = threadIdx.x; i < K4; i += blockDim.x) {
        float4 v = r[i];
        mx = fmaxf(mx, fmaxf(fmaxf(fabsf(v.x), fabsf(v.y)),
                             fmaxf(fabsf(v.z), fabsf(v.w))));
    }
    __shared__ float smax[8];
#pragma unroll
    for (int o = 16; o > 0; o >>= 1) mx = fmaxf(mx, __shfl_xor_sync(0xffffffffu, mx, o));
    if ((threadIdx.x & 31) == 0) smax[threadIdx.x >> 5] = mx;
    __syncthreads();
    if (threadIdx.x < 32) {
        float v = (threadIdx.x < 8) ? smax[threadIdx.x] : 0.f;
#pragma unroll
        for (int o = 4; o > 0; o >>= 1) v = fmaxf(v, __shfl_xor_sync(0xffffffffu, v, o));
        if (threadIdx.x == 0) smax[0] = v;
    }
    __syncthreads();
    const float m = smax[0];
    const float inv = (m > 0.f) ? 32512.f / m : 0.f;
    if (threadIdx.x == 0) scale[row] = (m > 0.f) ? m / 32512.f : 1.f;
    char4* p1 = (char4*)q1 + (size_t)row * K4;
    char4* p0 = (char4*)q0 + (size_t)row * K4;
    for (int i = threadIdx.x; i < K4; i += blockDim.x) {
        float4 v = r[i];
        int qx = __float2int_rn(v.x * inv), qy = __float2int_rn(v.y * inv);
        int qz = __float2int_rn(v.z * inv), qw = __float2int_rn(v.w * inv);
        int hx = (qx + 128) >> 8, hy = (qy + 128) >> 8;
        int hz = (qz + 128) >> 8, hw = (qw + 128) >> 8;
        p1[i] = make_char4((char)hx, (char)hy, (char)hz, (char)hw);
        p0[i] = make_char4((char)(qx - (hx << 8)), (char)(qy - (hy << 8)),
                           (char)(qz - (hz << 8)), (char)(qw - (hw << 8)));
    }
}

// ======================= small kernels =======================================
__global__ void zero_kernel() {
    int i = threadIdx.x;
    if (i < NE) { g_counts[i] = 0; g_cursor[i] = 0; g_importance[i] = 0.f; }
}

__global__ void router_kernel(const float* __restrict__ x,
                              const float* __restrict__ rw,
                              float* __restrict__ logits_out) {
    __shared__ float s_imp[NE];
    __shared__ int   s_cnt[NE];
    int tid = threadIdx.x;
    if (tid < NE) { s_imp[tid] = 0.f; s_cnt[tid] = 0; }
    __syncthreads();
    int warp = tid >> 5, lane = tid & 31;
    int t = blockIdx.x * 8 + warp;
    float acc[NE];
#pragma unroll
    for (int e = 0; e < NE; e++) acc[e] = 0.f;
    const float* xr = x + (size_t)t * H_DIM;
    for (int i = lane; i < H_DIM; i += 32) {
        float xv = xr[i];
#pragma unroll
        for (int e = 0; e < NE; e++) acc[e] += xv * rw[e * H_DIM + i];
    }
#pragma unroll
    for (int e = 0; e < NE; e++) {
#pragma unroll
        for (int o = 16; o > 0; o >>= 1) acc[e] += __shfl_xor_sync(0xffffffffu, acc[e], o);
    }
    if (lane == 0) {
        float mx = acc[0];
#pragma unroll
        for (int e = 1; e < NE; e++) mx = fmaxf(mx, acc[e]);
        float p[NE]; float s = 0.f;
#pragma unroll
        for (int e = 0; e < NE; e++) { p[e] = expf(acc[e] - mx); s += p[e]; }
        float inv = 1.f / s;
        int i0 = 0; float b0 = -1.f;
#pragma unroll
        for (int e = 0; e < NE; e++) {
            p[e] *= inv;
            logits_out[t * NE + e] = acc[e];
            if (p[e] > b0) { b0 = p[e]; i0 = e; }
        }
        int i1 = 0; float b1 = -1.f;
#pragma unroll
        for (int e = 0; e < NE; e++)
            if (e != i0 && p[e] > b1) { b1 = p[e]; i1 = e; }
        g_sel[t * 2] = i0; g_sel[t * 2 + 1] = i1;
        g_wts[t * 2] = b0; g_wts[t * 2 + 1] = b1;
#pragma unroll
        for (int e = 0; e < NE; e++) atomicAdd(&s_imp[e], p[e]);
        atomicAdd(&s_cnt[i0], 1); atomicAdd(&s_cnt[i1], 1);
    }
    __syncthreads();
    if (tid < NE) {
        atomicAdd(&g_importance[tid], s_imp[tid]);
        atomicAdd(&g_counts[tid], s_cnt[tid]);
    }
}

__global__ void offsets_kernel() {
    int off = 0;
    for (int e = 0; e < NE; e++) { g_offsets[e] = off; g_cursor[e] = off; off += g_counts[e]; }
    g_offsets[NE] = off;
}

__global__ void scatter_kernel() {
    int t = blockIdx.x * blockDim.x + threadIdx.x;
    if (t >= T_TOK) return;
#pragma unroll
    for (int k = 0; k < 2; k++) {
        int e = g_sel[t * 2 + k];
        int pos = atomicAdd(&g_cursor[e], 1);
        g_perm[pos] = t;
        g_cw[pos] = g_wts[t * 2 + k];
        g_eid[pos] = e;
        g_slot[t * 2 + k] = pos;
    }
}

__global__ void pg_kernel(const float* __restrict__ h1,
                          const float* __restrict__ pg) {
    int tid = threadIdx.x;
    int warp = tid >> 5, lane = tid & 31;
    int t = blockIdx.x * 8 + warp;
    float acc[NE];
#pragma unroll
    for (int e = 0; e < NE; e++) acc[e] = 0.f;
    const float* hr = h1 + (size_t)t * H_DIM;
    for (int i = lane; i < H_DIM; i += 32) {
        float hv = hr[i];
#pragma unroll
        for (int e = 0; e < NE; e++) acc[e] += hv * pg[e * H_DIM + i];
    }
#pragma unroll
    for (int e = 0; e < NE; e++) {
#pragma unroll
        for (int o = 16; o > 0; o >>= 1) acc[e] += __shfl_xor_sync(0xffffffffu, acc[e], o);
    }
    if (lane == 0) {
#pragma unroll
        for (int e = 0; e < NE; e++)
            g_gate[t * NE + e] = 1.f / (1.f + expf(-acc[e]));
    }
}

__global__ void gval_kernel() {
    int s = blockIdx.x * blockDim.x + threadIdx.x;
    if (s >= TK) return;
    g_gval[s] = g_gate[g_perm[s] * NE + g_eid[s]];
}

__global__ void combine_kernel(float* __restrict__ out) {
    int idx = blockIdx.x * blockDim.x + threadIdx.x;
    int t = idx / (H_DIM / 4);
    int c = (idx % (H_DIM / 4)) * 4;
    int s0 = g_slot[t * 2], s1 = g_slot[t * 2 + 1];
    float4 a = *(const float4*)&g_yout[(size_t)s0 * H_DIM + c];
    float4 b = *(const float4*)&g_yout[(size_t)s1 * H_DIM + c];
    *(float4*)&out[(size_t)t * H_DIM + c] =
        make_float4(a.x + b.x, a.y + b.y, a.z + b.z, a.w + b.w);
}

__global__ void aux_kernel(float* __restrict__ out_aux) {
    float imps = 0.f, lds = 0.f;
    float imp[NE], ld[NE];
    for (int e = 0; e < NE; e++) {
        imp[e] = g_importance[e]; ld[e] = (float)g_counts[e];
        imps += imp[e]; lds += ld[e];
    }
    float a = 0.f;
    for (int e = 0; e < NE; e++)
        a += (imp[e] / (imps + 1e-9f)) * (ld[e] / (lds + 1e-9f));
    *out_aux = (float)NE * a;
}

// ======================= two-limb int8 IMMA GEMM =============================
// C[M,N] = A[M,K] @ B[N,K]^T with A = sA*(a1*256+a0), B = sB*(b1*256+b0):
//   val = sA*sB*(65536*S(a1b1) + 256*S(a1b0 + a0b1)), a0b0 dropped (~1e-4 rel)
// 128x128 CTA tile, K-chunk 64 int8, 8 warps (2x4), warp tile 64x32,
// mma.sync m16n8k32 s8 + ldmatrix.  SMEM rows 80B -> conflict-free ldmatrix.
// MODE 0: relu(val)        (u)
// MODE 1: val              (h1)
// MODE 2: relu(gval*val)   (expert gate, A rows gathered via perm)
// MODE 3: cw*val           (expert down, A rows contiguous slots)
#define BM 128
#define BN 128
#define BKB 64
#define ROWB 80
#define ARR_B (128 * ROWB)               // 10240 per limb array
#define STAGE_B (4 * ARR_B)              // A1|A0|B1|B0 = 40960
#define GSMEM (2 * STAGE_B)              // 81920

template<int MODE>
__global__ void __launch_bounds__(256, 1) gemm_i8(
    const int8_t* __restrict__ A1, const int8_t* __restrict__ A0,
    const float* __restrict__ sA,
    const int8_t* __restrict__ B1, const int8_t* __restrict__ B0,
    const float* __restrict__ sB,
    float* __restrict__ Of, int N, int K, size_t strideB) {
    extern __shared__ char smem[];
    const int tid = threadIdx.x;
    const int wid = tid >> 5, lane = tid & 31;
    const int warp_m = wid & 1;          // 2 warps over M (64 rows each)
    const int warp_n = wid >> 1;         // 4 warps over N (32 cols each)

    int cnt = BM, base = 0;
    const int m0i = blockIdx.x * BM;
    const int n0i = blockIdx.y * BN;
    if (MODE >= 2) {
        const int e = blockIdx.z;
        cnt = g_counts[e]; base = g_offsets[e];
        if (m0i >= cnt) return;
        B1 += (size_t)e * strideB;
        B0 += (size_t)e * strideB;
        sB += (size_t)e * N;
    }

    // ---- gmem->smem mapping: 2 threads per row, each 32B (2x16B) ------------
    const int lr = tid >> 1;             // row 0..127
    const int lc = tid & 1;              // 32B half
    long aRow;
    if (MODE == 2) { int r = m0i + lr; aRow = (r < cnt) ? (long)g_perm[base + r] : -1; }
    else if (MODE == 3) { int r = m0i + lr; aRow = (r < cnt) ? (long)(base + r) : -1; }
    else aRow = (long)(m0i + lr);
    const uint32_t aSz = (aRow >= 0) ? 16u : 0u;
    const size_t aRowC = (size_t)(aRow >= 0 ? aRow : 0);
    const size_t bRow = (size_t)(n0i + lr);

    const uint32_t sb = smem_u32(smem);
    const uint32_t dOff = (uint32_t)lr * ROWB + (uint32_t)lc * 32;

    // ---- ldmatrix lane addresses (byte-granular K) ---------------------------
    const int rA = (lane & 7) + ((lane >> 3) & 1) * 8;
    const uint32_t kcA = (uint32_t)(lane >> 4) * 16;
    uint32_t aoff[4];
#pragma unroll
    for (int mt = 0; mt < 4; mt++)
        aoff[mt] = (uint32_t)(warp_m * 64 + mt * 16 + rA) * ROWB + kcA;
    uint32_t boff[2];                    // each x4 covers two n-tiles (16 rows)
#pragma unroll
    for (int p = 0; p < 2; p++)
        boff[p] = (uint32_t)(warp_n * 32 + p * 16 + ((lane >> 4) & 1) * 8 + (lane & 7)) * ROWB
                + (uint32_t)((lane >> 3) & 1) * 16;

    int acc1[4][4][4], acc2[4][4][4];
#pragma unroll
    for (int mt = 0; mt < 4; mt++)
#pragma unroll
        for (int nt = 0; nt < 4; nt++)
#pragma unroll
            for (int q = 0; q < 4; q++) { acc1[mt][nt][q] = 0; acc2[mt][nt][q] = 0; }

    const int nk = K / BKB;

#define PREFETCH(stage, cIdx) do {                                               \
        const size_t ko = (size_t)(cIdx) * BKB + (size_t)lc * 32;                \
        const uint32_t d0 = sb + (stage) * STAGE_B + dOff;                       \
        const int8_t* pa1 = A1 + aRowC * K + ko;                                 \
        const int8_t* pa0 = A0 + aRowC * K + ko;                                 \
        CP_ASYNC16(d0,               pa1,      aSz);                             \
        CP_ASYNC16(d0 + 16,          pa1 + 16, aSz);                             \
        CP_ASYNC16(d0 + ARR_B,       pa0,      aSz);                             \
        CP_ASYNC16(d0 + ARR_B + 16,  pa0 + 16, aSz);                             \
        const int8_t* pb1 = B1 + bRow * K + ko;                                  \
        const int8_t* pb0 = B0 + bRow * K + ko;                                  \
        CP_ASYNC16(d0 + 2*ARR_B,      pb1,      16u);                            \
        CP_ASYNC16(d0 + 2*ARR_B + 16, pb1 + 16, 16u);                            \
        CP_ASYNC16(d0 + 3*ARR_B,      pb0,      16u);                            \
        CP_ASYNC16(d0 + 3*ARR_B + 16, pb0 + 16, 16u);                            \
    } while (0)

    PREFETCH(0, 0);
    CP_COMMIT();

    for (int c = 0; c < nk; ++c) {
        if (c + 1 < nk) {
            PREFETCH((c + 1) & 1, c + 1);
            CP_COMMIT();
            CP_WAIT(1);
        } else {
            CP_WAIT(0);
        }
        __syncthreads();
        const uint32_t st = sb + (uint32_t)(c & 1) * STAGE_B;
#pragma unroll
        for (int ks = 0; ks < 2; ++ks) {
            const uint32_t kb = (uint32_t)ks * 32;
            uint32_t a1f[4][4], a0f[4][4], b1f[2][4], b0f[2][4];
#pragma unroll
            for (int mt = 0; mt < 4; mt++) {
                LDSM4(a1f[mt][0], a1f[mt][1], a1f[mt][2], a1f[mt][3],
                      st + aoff[mt] + kb);
                LDSM4(a0f[mt][0], a0f[mt][1], a0f[mt][2], a0f[mt][3],
                      st + ARR_B + aoff[mt] + kb);
            }
#pragma unroll
            for (int p = 0; p < 2; p++) {
                LDSM4(b1f[p][0], b1f[p][1], b1f[p][2], b1f[p][3],
                      st + 2 * ARR_B + boff[p] + kb);
                LDSM4(b0f[p][0], b0f[p][1], b0f[p][2], b0f[p][3],
                      st + 3 * ARR_B + boff[p] + kb);
            }
#pragma unroll
            for (int mt = 0; mt < 4; mt++)
#pragma unroll
                for (int nt = 0; nt < 4; nt++) {
                    const int p = nt >> 1, w = (nt & 1) * 2;
                    MMAS8(acc1[mt][nt], a1f[mt][0], a1f[mt][1], a1f[mt][2], a1f[mt][3],
                          b1f[p][w], b1f[p][w + 1]);
                    MMAS8(acc2[mt][nt], a1f[mt][0], a1f[mt][1], a1f[mt][2], a1f[mt][3],
                          b0f[p][w], b0f[p][w + 1]);
                    MMAS8(acc2[mt][nt], a0f[mt][0], a0f[mt][1], a0f[mt][2], a0f[mt][3],
                          b1f[p][w], b1f[p][w + 1]);
                }
        }
        __syncthreads();
    }
#undef PREFETCH

    // ---- epilogue ------------------------------------------------------------
    const int colBase = n0i + warp_n * 32 + (lane & 3) * 2;
#pragma unroll
    for (int mt = 0; mt < 4; mt++) {
#pragma unroll
        for (int h = 0; h < 2; h++) {
            const int rloc = warp_m * 64 + mt * 16 + (lane >> 2) + h * 8;
            const int r = m0i + rloc;
            size_t orow;
            float rowScale, mscale = 1.f;
            if (MODE >= 2) {
                if (r >= cnt) continue;
                orow = (size_t)base + r;
                if (MODE == 2) { rowScale = sA[g_perm[orow]]; mscale = g_gval[orow]; }
                else           { rowScale = sA[orow];         mscale = g_cw[orow]; }
            } else {
                orow = (size_t)r;
                rowScale = sA[r];
            }
#pragma unroll
            for (int nt = 0; nt < 4; nt++) {
                const int c0 = colBase + nt * 8;
                float v0 = rowScale * sB[c0] *
                           (65536.f * (float)acc1[mt][nt][h * 2] +
                              256.f * (float)acc2[mt][nt][h * 2]);
                float v1 = rowScale * sB[c0 + 1] *
                           (65536.f * (float)acc1[mt][nt][h * 2 + 1] +
                              256.f * (float)acc2[mt][nt][h * 2 + 1]);
                if (MODE == 0) { v0 = fmaxf(v0, 0.f); v1 = fmaxf(v1, 0.f); }
                else if (MODE == 2) { v0 = fmaxf(mscale * v0, 0.f); v1 = fmaxf(mscale * v1, 0.f); }
                else if (MODE == 3) { v0 *= mscale; v1 *= mscale; }
                *(float2*)(Of + orow * N + c0) = make_float2(v0, v1);
            }
        }
    }
}

// ======================= launch ==============================================
extern "C" void kernel_launch(void* const* d_in, const int* in_sizes, int n_in,
                              void* d_out, int out_size) {
    const float* x  = (const float*)d_in[0];  // [T, H]
    const float* rw = (const float*)d_in[1];  // [E, H]
    const float* sg = (const float*)d_in[2];  // [HS, H]
    const float* sd = (const float*)d_in[3];  // [H, HS]
    const float* pg = (const float*)d_in[4];  // [E, H]
    const float* gw = (const float*)d_in[5];  // [E, P, H]
    const float* dw = (const float*)d_in[6];  // [E, H, P]

    float* out        = (float*)d_out;
    float* out_logits = out + (size_t)T_TOK * H_DIM;
    float* out_aux    = out_logits + (size_t)T_TOK * NE;

    int8_t *x1, *x0, *sg1, *sg0, *sd1, *sd0, *gw1, *gw0, *dw1, *dw0,
           *u1, *u0, *h11, *h10, *a1, *a0;
    float *sx, *ssg, *ssd, *sgw, *sdw, *su, *sh1, *sact, *u, *h1, *act, *yout;
    cudaGetSymbolAddress((void**)&x1, g_x1);   cudaGetSymbolAddress((void**)&x0, g_x0);
    cudaGetSymbolAddress((void**)&sx, g_sx);
    cudaGetSymbolAddress((void**)&sg1, g_sg1); cudaGetSymbolAddress((void**)&sg0, g_sg0);
    cudaGetSymbolAddress((void**)&ssg, g_ssg);
    cudaGetSymbolAddress((void**)&sd1, g_sd1); cudaGetSymbolAddress((void**)&sd0, g_sd0);
    cudaGetSymbolAddress((void**)&ssd, g_ssd);
    cudaGetSymbolAddress((void**)&gw1, g_gw1); cudaGetSymbolAddress((void**)&gw0, g_gw0);
    cudaGetSymbolAddress((void**)&sgw, g_sgw);
    cudaGetSymbolAddress((void**)&dw1, g_dw1); cudaGetSymbolAddress((void**)&dw0, g_dw0);
    cudaGetSymbolAddress((void**)&sdw, g_sdw);
    cudaGetSymbolAddress((void**)&u1, g_u1);   cudaGetSymbolAddress((void**)&u0, g_u0);
    cudaGetSymbolAddress((void**)&su, g_su);   cudaGetSymbolAddress((void**)&u, g_u);
    cudaGetSymbolAddress((void**)&h11, g_h11); cudaGetSymbolAddress((void**)&h10, g_h10);
    cudaGetSymbolAddress((void**)&sh1, g_sh1); cudaGetSymbolAddress((void**)&h1, g_h1);
    cudaGetSymbolAddress((void**)&a1, g_a1);   cudaGetSymbolAddress((void**)&a0, g_a0);
    cudaGetSymbolAddress((void**)&sact, g_sact); cudaGetSymbolAddress((void**)&act, g_act);
    cudaGetSymbolAddress((void**)&yout, g_yout);

    cudaFuncSetAttribute(gemm_i8<0>, cudaFuncAttributeMaxDynamicSharedMemorySize, GSMEM);
    cudaFuncSetAttribute(gemm_i8<1>, cudaFuncAttributeMaxDynamicSharedMemorySize, GSMEM);
    cudaFuncSetAttribute(gemm_i8<2>, cudaFuncAttributeMaxDynamicSharedMemorySize, GSMEM);
    cudaFuncSetAttribute(gemm_i8<3>, cudaFuncAttributeMaxDynamicSharedMemorySize, GSMEM);

    // quantize inputs / weights (per-row over K)
    quant_rows<<<T_TOK,  256>>>(x,  H_DIM / 4,  x1,  x0,  sx);
    quant_rows<<<HS_DIM, 256>>>(sg, H_DIM / 4,  sg1, sg0, ssg);
    quant_rows<<<H_DIM,  256>>>(sd, HS_DIM / 4, sd1, sd0, ssd);
    quant_rows<<<NE * P_DIM, 256>>>(gw, H_DIM / 4, gw1, gw0, sgw);
    quant_rows<<<NE * H_DIM, 256>>>(dw, P_DIM / 4, dw1, dw0, sdw);

    zero_kernel<<<1, 32>>>();
    router_kernel<<<T_TOK / 8, 256>>>(x, rw, out_logits);
    offsets_kernel<<<1, 1>>>();
    scatter_kernel<<<T_TOK / 256, 256>>>();

    // u = relu(x @ sg^T)   [T, HS]
    {
        dim3 g(T_TOK / BM, HS_DIM / BN);
        gemm_i8<0><<<g, 256, GSMEM>>>(x1, x0, sx, sg1, sg0, ssg, u,
                                      HS_DIM, H_DIM, 0);
    }
    quant_rows<<<T_TOK, 256>>>(u, HS_DIM / 4, u1, u0, su);

    // h1 = u @ sd^T        [T, H]
    {
        dim3 g(T_TOK / BM, H_DIM / BN);
        gemm_i8<1><<<g, 256, GSMEM>>>(u1, u0, su, sd1, sd0, ssd, h1,
                                      H_DIM, HS_DIM, 0);
    }
    pg_kernel<<<T_TOK / 8, 256>>>(h1, pg);
    gval_kernel<<<TK / 256, 256>>>();
    quant_rows<<<T_TOK, 256>>>(h1, H_DIM / 4, h11, h10, sh1);

    // act = relu(g * (h1[perm] @ g_w[e]^T))   [TK, P]
    {
        dim3 g(T_TOK / BM, P_DIM / BN, NE);
        gemm_i8<2><<<g, 256, GSMEM>>>(h11, h10, sh1, gw1, gw0, sgw, act,
                                      P_DIM, H_DIM, (size_t)P_DIM * H_DIM);
    }
    quant_rows<<<TK, 256>>>(act, P_DIM / 4, a1, a0, sact);

    // yout = cw * (act @ d_w[e]^T)            [TK, H]
    {
        dim3 g(T_TOK / BM, H_DIM / BN, NE);
        gemm_i8<3><<<g, 256, GSMEM>>>(a1, a0, sact, dw1, dw0, sdw, yout,
                                      H_DIM, P_DIM, (size_t)H_DIM * P_DIM);
    }
    combine_kernel<<<(T_TOK * H_DIM / 4) / 256, 256>>>(out);
    aux_kernel<<<1, 1>>>(out_aux);
}